// round 13
// baseline (speedup 1.0000x reference)
#include <cuda_runtime.h>
#include <cuda_bf16.h>
#include <math.h>
#include <stdint.h>

#define TTOK   512
#define NHD    64
#define DMODEL 576
#define DV     512
#define TOPKN  512
#define NKV    32768
#define NTHR   512
#define SCALE_F 0.041666666666666664f   // 576^-0.5

// ---------------- device scratch (bf16 hi/lo split of kv_cache) ----------------
__device__ __nv_bfloat16 g_khi[(size_t)NKV * DMODEL];
__device__ __nv_bfloat16 g_klo[(size_t)NKV * DMODEL];

// ---------------- smem layout (bytes) ----------------
#define SM_IDX   0            // 512 ints
#define SM_REDM  2048         // 64x4 floats
#define SM_REDS  3072         // 64x4 floats
#define SM_LH    4096         // 64 floats
// phase 1: Q buffers [64h x 32d] hi/lo (stride 40 bf16 = 80B), K buffers [512k x 32d] hi/lo
#define QB0      4608         // per buffer: hi 5120 + lo 5120 = 10240; x2 -> ends 25088
#define KB0      25088        // per buffer: hi 40960 + lo 40960 = 81920; x2 -> ends 188928
// phase 2 (union, after GEMM1): P [64h x 512k] hi/lo (stride 520 bf16 = 1040B)
#define P_HI     4608         // 66560
#define P_LO     71168        // 66560 -> ends 137728
#define VB0      137728       // per buffer: hi 16640 + lo 16640 = 33280; x2 -> ends 204288
#define SMEM_TOTAL 204288

// ---------------- helpers ----------------
__device__ __forceinline__ uint32_t smem_u32(const void* p) {
    uint32_t a;
    asm("{ .reg .u64 t; cvta.to.shared.u64 t, %1; cvt.u32.u64 %0, t; }" : "=r"(a) : "l"(p));
    return a;
}
__device__ __forceinline__ void ldsm_x4(uint32_t* r, uint32_t addr) {
    asm volatile("ldmatrix.sync.aligned.m8n8.x4.shared.b16 {%0,%1,%2,%3}, [%4];"
                 : "=r"(r[0]), "=r"(r[1]), "=r"(r[2]), "=r"(r[3]) : "r"(addr));
}
__device__ __forceinline__ void ldsm_x4t(uint32_t* r, uint32_t addr) {
    asm volatile("ldmatrix.sync.aligned.m8n8.x4.trans.shared.b16 {%0,%1,%2,%3}, [%4];"
                 : "=r"(r[0]), "=r"(r[1]), "=r"(r[2]), "=r"(r[3]) : "r"(addr));
}
__device__ __forceinline__ void mma_bf16(float* c, const uint32_t* a, uint32_t b0, uint32_t b1) {
    asm volatile("mma.sync.aligned.m16n8k16.row.col.f32.bf16.bf16.f32 "
                 "{%0,%1,%2,%3}, {%4,%5,%6,%7}, {%8,%9}, {%0,%1,%2,%3};"
                 : "+f"(c[0]), "+f"(c[1]), "+f"(c[2]), "+f"(c[3])
                 : "r"(a[0]), "r"(a[1]), "r"(a[2]), "r"(a[3]), "r"(b0), "r"(b1));
}
__device__ __forceinline__ void cp16(uint32_t dst, const void* src) {
    asm volatile("cp.async.cg.shared.global [%0], [%1], 16;" :: "r"(dst), "l"(src));
}
#define CP_COMMIT() asm volatile("cp.async.commit_group;" ::: "memory")
#define CP_WAIT0()  asm volatile("cp.async.wait_group 0;" ::: "memory")

// ---------------- kv conversion pre-kernel ----------------
__global__ void conv_kv_kernel(const float4* __restrict__ src) {
    int i = blockIdx.x * blockDim.x + threadIdx.x;
    float4 v = src[i];
    __nv_bfloat16 h0 = __float2bfloat16_rn(v.x), h1 = __float2bfloat16_rn(v.y);
    __nv_bfloat16 h2 = __float2bfloat16_rn(v.z), h3 = __float2bfloat16_rn(v.w);
    __nv_bfloat162* hi = (__nv_bfloat162*)g_khi;
    __nv_bfloat162* lo = (__nv_bfloat162*)g_klo;
    hi[2*i]   = __nv_bfloat162(h0, h1);
    hi[2*i+1] = __nv_bfloat162(h2, h3);
    lo[2*i]   = __nv_bfloat162(__float2bfloat16_rn(v.x - __bfloat162float(h0)),
                               __float2bfloat16_rn(v.y - __bfloat162float(h1)));
    lo[2*i+1] = __nv_bfloat162(__float2bfloat16_rn(v.z - __bfloat162float(h2)),
                               __float2bfloat16_rn(v.w - __bfloat162float(h3)));
}

// ---------------- main attention kernel ----------------
__global__ __launch_bounds__(NTHR, 1)
void mla_mma_kernel(const float* __restrict__ qg,
                    const int* __restrict__ topk,
                    const float* __restrict__ sink,
                    float* __restrict__ outg)
{
    extern __shared__ char smem[];
    const uint32_t sbase = smem_u32(smem);
    const int tid  = threadIdx.x;
    const int lane = tid & 31;
    const int w    = tid >> 5;
    const int hb   = w & 3;          // head block (16 heads)
    const int g    = w >> 2;         // 128-key / 128-dv slice
    const int t    = blockIdx.x;

    int*   idx_s = (int*)(smem + SM_IDX);
    float* redm  = (float*)(smem + SM_REDM);
    float* reds  = (float*)(smem + SM_REDS);
    float* lh    = (float*)(smem + SM_LH);

    idx_s[tid] = topk[(size_t)t * TOPKN + tid];
    __syncthreads();

    float acc[16][4];
    #pragma unroll
    for (int i = 0; i < 16; ++i)
        #pragma unroll
        for (int j = 0; j < 4; ++j) acc[i][j] = 0.f;

    const int lo16 = lane & 15, hi16 = lane >> 4;

    // ---- loader lambdas ----
    auto loadQ = [&](int dc, int b) {
        int row = tid >> 3, q = tid & 7;
        float4 v = *(const float4*)(qg + (size_t)(t * NHD + row) * DMODEL + dc * 32 + q * 4);
        __nv_bfloat16 h0 = __float2bfloat16_rn(v.x), h1 = __float2bfloat16_rn(v.y);
        __nv_bfloat16 h2 = __float2bfloat16_rn(v.z), h3 = __float2bfloat16_rn(v.w);
        char* dst = smem + QB0 + b * 10240 + row * 80 + q * 8;
        *(__nv_bfloat162*)(dst)          = __nv_bfloat162(h0, h1);
        *(__nv_bfloat162*)(dst + 4)      = __nv_bfloat162(h2, h3);
        *(__nv_bfloat162*)(dst + 5120)   = __nv_bfloat162(__float2bfloat16_rn(v.x - __bfloat162float(h0)),
                                                          __float2bfloat16_rn(v.y - __bfloat162float(h1)));
        *(__nv_bfloat162*)(dst + 5124)   = __nv_bfloat162(__float2bfloat16_rn(v.z - __bfloat162float(h2)),
                                                          __float2bfloat16_rn(v.w - __bfloat162float(h3)));
    };
    auto issueK = [&](int dc, int b) {
        int rb = tid >> 3, q = tid & 7;
        int half = q >> 2, s = q & 3;
        uint32_t base = sbase + KB0 + b * 81920 + half * 40960;
        const __nv_bfloat16* gk = half ? g_klo : g_khi;
        #pragma unroll
        for (int pass = 0; pass < 8; ++pass) {
            int krow = pass * 64 + rb;
            int id = idx_s[krow]; id = id < 0 ? 0 : id;
            cp16(base + krow * 80 + s * 16, gk + (size_t)id * DMODEL + dc * 32 + s * 8);
        }
    };
    auto issueV = [&](int vt, int b) {
        int row = tid >> 5;
        int id = idx_s[vt * 16 + row]; id = id < 0 ? 0 : id;
        #pragma unroll
        for (int j = 0; j < 4; ++j) {
            int seg = lane + 32 * j;
            int half = seg >> 6, s = seg & 63;
            const __nv_bfloat16* gk = half ? g_klo : g_khi;
            cp16(sbase + VB0 + b * 33280 + half * 16640 + row * 1040 + s * 16,
                 gk + (size_t)id * DMODEL + s * 8);
        }
    };

    // ================= GEMM1: S = Q K^T, 18 d-chunks of 32, one sync/iter =================
    loadQ(0, 0); issueK(0, 0); CP_COMMIT();
    int buf = 0;
    #pragma unroll 1
    for (int dc = 0; dc < 18; ++dc) {
        CP_WAIT0();
        __syncthreads();   // data ready for all threads; prior iteration's reads complete
        if (dc + 1 < 18) { loadQ(dc + 1, buf ^ 1); issueK(dc + 1, buf ^ 1); CP_COMMIT(); }
        {
            uint32_t qb = sbase + QB0 + buf * 10240 + (16 * hb + lo16) * 80 + hi16 * 16;
            uint32_t kb = sbase + KB0 + buf * 81920 + (128 * g + lo16) * 80 + hi16 * 16;
            #pragma unroll
            for (int kk = 0; kk < 2; ++kk) {
                uint32_t aH[4], aL[4];
                ldsm_x4(aH, qb + kk * 32);
                ldsm_x4(aL, qb + 5120 + kk * 32);
                uint32_t bH[2][4], bL[2][4];
                ldsm_x4(bH[0], kb + kk * 32);
                ldsm_x4(bL[0], kb + 40960 + kk * 32);
                #pragma unroll
                for (int np = 0; np < 8; ++np) {
                    int cur = np & 1, nxt = cur ^ 1;
                    if (np < 7) {
                        ldsm_x4(bH[nxt], kb + (np + 1) * 1280 + kk * 32);
                        ldsm_x4(bL[nxt], kb + 40960 + (np + 1) * 1280 + kk * 32);
                    }
                    // interleave the two acc chains; per-chain order unchanged (H.H, H.L, L.H)
                    mma_bf16(acc[2*np],   aH, bH[cur][0], bH[cur][2]);
                    mma_bf16(acc[2*np+1], aH, bH[cur][1], bH[cur][3]);
                    mma_bf16(acc[2*np],   aH, bL[cur][0], bL[cur][2]);
                    mma_bf16(acc[2*np+1], aH, bL[cur][1], bL[cur][3]);
                    mma_bf16(acc[2*np],   aL, bH[cur][0], bH[cur][2]);
                    mma_bf16(acc[2*np+1], aL, bH[cur][1], bH[cur][3]);
                }
            }
        }
        buf ^= 1;
    }
    __syncthreads();   // all GEMM1 smem reads done before V0 overwrites K-buffer region

    // issue V tile 0 load now (K/Q buffers dead; overlaps softmax)
    issueV(0, 0); CP_COMMIT();

    // ================= softmax on register fragments =================
    const int r0 = lane >> 2;
    const int h0 = 16 * hb + r0, h1 = h0 + 8;
    const int c0 = 2 * (lane & 3);
    float m0 = -1e30f, m1 = -1e30f;
    uint32_t vm = 0;
    #pragma unroll
    for (int nt = 0; nt < 16; ++nt) {
        int key = 128 * g + 8 * nt + c0;
        bool v0 = idx_s[key] >= 0, v1 = idx_s[key + 1] >= 0;
        acc[nt][0] *= SCALE_F; acc[nt][1] *= SCALE_F;
        acc[nt][2] *= SCALE_F; acc[nt][3] *= SCALE_F;
        if (v0) { m0 = fmaxf(m0, acc[nt][0]); m1 = fmaxf(m1, acc[nt][2]); vm |= 1u << (2*nt); }
        if (v1) { m0 = fmaxf(m0, acc[nt][1]); m1 = fmaxf(m1, acc[nt][3]); vm |= 2u << (2*nt); }
    }
    m0 = fmaxf(m0, __shfl_xor_sync(0xffffffffu, m0, 1));
    m0 = fmaxf(m0, __shfl_xor_sync(0xffffffffu, m0, 2));
    m1 = fmaxf(m1, __shfl_xor_sync(0xffffffffu, m1, 1));
    m1 = fmaxf(m1, __shfl_xor_sync(0xffffffffu, m1, 2));
    if ((lane & 3) == 0) { redm[h0 * 4 + g] = m0; redm[h1 * 4 + g] = m1; }
    __syncthreads();
    float sk0 = sink[h0], sk1 = sink[h1];
    float mf0 = fmaxf(fmaxf(fmaxf(redm[h0*4+0], redm[h0*4+1]), fmaxf(redm[h0*4+2], redm[h0*4+3])), sk0);
    float mf1 = fmaxf(fmaxf(fmaxf(redm[h1*4+0], redm[h1*4+1]), fmaxf(redm[h1*4+2], redm[h1*4+3])), sk1);
    float l0 = 0.f, l1 = 0.f;
    #pragma unroll
    for (int nt = 0; nt < 16; ++nt) {
        int key = 128 * g + 8 * nt + c0;
        float p00 = ((vm >> (2*nt)) & 1) ? __expf(acc[nt][0] - mf0) : 0.f;
        float p01 = ((vm >> (2*nt)) & 2) ? __expf(acc[nt][1] - mf0) : 0.f;
        float p10 = ((vm >> (2*nt)) & 1) ? __expf(acc[nt][2] - mf1) : 0.f;
        float p11 = ((vm >> (2*nt)) & 2) ? __expf(acc[nt][3] - mf1) : 0.f;
        l0 += p00 + p01; l1 += p10 + p11;
        __nv_bfloat16 a0 = __float2bfloat16_rn(p00), a1 = __float2bfloat16_rn(p01);
        __nv_bfloat16 b0 = __float2bfloat16_rn(p10), b1 = __float2bfloat16_rn(p11);
        *(__nv_bfloat162*)(smem + P_HI + h0 * 1040 + key * 2) = __nv_bfloat162(a0, a1);
        *(__nv_bfloat162*)(smem + P_HI + h1 * 1040 + key * 2) = __nv_bfloat162(b0, b1);
        *(__nv_bfloat162*)(smem + P_LO + h0 * 1040 + key * 2) =
            __nv_bfloat162(__float2bfloat16_rn(p00 - __bfloat162float(a0)),
                           __float2bfloat16_rn(p01 - __bfloat162float(a1)));
        *(__nv_bfloat162*)(smem + P_LO + h1 * 1040 + key * 2) =
            __nv_bfloat162(__float2bfloat16_rn(p10 - __bfloat162float(b0)),
                           __float2bfloat16_rn(p11 - __bfloat162float(b1)));
    }
    l0 += __shfl_xor_sync(0xffffffffu, l0, 1);
    l0 += __shfl_xor_sync(0xffffffffu, l0, 2);
    l1 += __shfl_xor_sync(0xffffffffu, l1, 1);
    l1 += __shfl_xor_sync(0xffffffffu, l1, 2);
    if ((lane & 3) == 0) { reds[h0 * 4 + g] = l0; reds[h1 * 4 + g] = l1; }
    __syncthreads();
    if (g == 0 && (lane & 3) == 0) {
        float la = reds[h0*4+0] + reds[h0*4+1] + reds[h0*4+2] + reds[h0*4+3] + __expf(sk0 - mf0);
        float lb = reds[h1*4+0] + reds[h1*4+1] + reds[h1*4+2] + reds[h1*4+3] + __expf(sk1 - mf1);
        lh[h0] = 1.0f / la;
        lh[h1] = 1.0f / lb;
    }

    // zero accumulators for GEMM2
    #pragma unroll
    for (int i = 0; i < 16; ++i)
        #pragma unroll
        for (int j = 0; j < 4; ++j) acc[i][j] = 0.f;

    // ================= GEMM2: O = P V, 32 key tiles of 16, one sync/iter =================
    int vbuf = 0;
    #pragma unroll 1
    for (int vt = 0; vt < 32; ++vt) {
        CP_WAIT0();
        __syncthreads();   // V tile ready; prior tile's reads complete; (vt==0) orders P + lh
        if (vt + 1 < 32) { issueV(vt + 1, vbuf ^ 1); CP_COMMIT(); }
        {
            uint32_t ap = sbase + P_HI + (16 * hb + lo16) * 1040 + hi16 * 16 + vt * 32;
            uint32_t vb = sbase + VB0 + vbuf * 33280 + lo16 * 1040 + hi16 * 16 + 256 * g;
            uint32_t aH[4], aL[4];
            ldsm_x4(aH, ap);
            ldsm_x4(aL, ap + 66560);
            uint32_t bH[2][4], bL[2][4];
            ldsm_x4t(bH[0], vb);
            ldsm_x4t(bL[0], vb + 16640);
            #pragma unroll
            for (int np = 0; np < 8; ++np) {
                int cur = np & 1, nxt = cur ^ 1;
                if (np < 7) {
                    ldsm_x4t(bH[nxt], vb + (np + 1) * 32);
                    ldsm_x4t(bL[nxt], vb + 16640 + (np + 1) * 32);
                }
                mma_bf16(acc[2*np],   aH, bH[cur][0], bH[cur][1]);
                mma_bf16(acc[2*np+1], aH, bH[cur][2], bH[cur][3]);
                mma_bf16(acc[2*np],   aH, bL[cur][0], bL[cur][1]);
                mma_bf16(acc[2*np+1], aH, bL[cur][2], bL[cur][3]);
                mma_bf16(acc[2*np],   aL, bH[cur][0], bH[cur][1]);
                mma_bf16(acc[2*np+1], aL, bH[cur][2], bH[cur][3]);
            }
        }
        vbuf ^= 1;
    }

    // ================= normalize + write =================
    float li0 = lh[h0], li1 = lh[h1];
    float* ob0 = outg + ((size_t)t * NHD + h0) * DV + 128 * g + c0;
    float* ob1 = outg + ((size_t)t * NHD + h1) * DV + 128 * g + c0;
    #pragma unroll
    for (int nt = 0; nt < 16; ++nt) {
        float2 v0 = make_float2(acc[nt][0] * li0, acc[nt][1] * li0);
        float2 v1 = make_float2(acc[nt][2] * li1, acc[nt][3] * li1);
        *(float2*)(ob0 + 8 * nt) = v0;
        *(float2*)(ob1 + 8 * nt) = v1;
    }
}

// ---------------- launcher ----------------
extern "C" void kernel_launch(void* const* d_in, const int* in_sizes, int n_in,
                              void* d_out, int out_size)
{
    const float* q    = (const float*)d_in[0];
    const float* kv   = (const float*)d_in[1];
    const int*   topk = (const int*)d_in[2];
    const float* sink = (const float*)d_in[3];
    float* out = (float*)d_out;

    const int n4 = 4718592;   // 32768*576/4
    conv_kv_kernel<<<n4 / 256, 256>>>((const float4*)kv);

    cudaFuncSetAttribute(mla_mma_kernel,
                         cudaFuncAttributeMaxDynamicSharedMemorySize, SMEM_TOTAL);
    mla_mma_kernel<<<TTOK, NTHR, SMEM_TOTAL>>>(q, topk, sink, out);
}